// round 11
// baseline (speedup 1.0000x reference)
#include <cuda_runtime.h>
#include <cuda_fp16.h>

// Problem constants: B=2, t=5, C=16, G=64
#define G 64
#define GG 4096
#define GGG 262144
#define NCH 16
#define CVOL (NCH * GGG)
#define NPAIR 8

// fp16 PAIR-entry tile, double buffered. Entry (z,y,x) = (h[x], h[x+1]), 4B.
// XP2=24 entries/row: warp's 4 y-rows hit disjoint 8-bank ranges {0,16,8,24}.
// ZS2=364 (15 rows x 24 + pad; mod 32 = 12, mult of 4): z-differing lanes
// offset by 12 banks; 16B STS alignment preserved. 15 z-planes suffice
// (AABB span <= 15 provably).
#define XP2 24
#define ZS2 364
#define TILE_E (15 * ZS2)  // 5460 entries * 4B = 21840 B per buffer

__device__ float g_M[NPAIR][12];

__global__ void xform_kernel(const float* __restrict__ poses /* (2,5,4,4) */) {
    int n = threadIdx.x;
    if (n >= NPAIR) return;
    int b = n >> 2;
    int k = (n & 3) + 1;
    const float* P0 = poses + (size_t)(b * 5 + 0) * 16;
    const float* P1 = poses + (size_t)(b * 5 + k) * 16;

    // T = P0 @ inv(P1); P1 rigid => inv(P1) = [R1^T | -R1^T t1]
    float R[3][3], t[3];
#pragma unroll
    for (int i = 0; i < 3; i++)
#pragma unroll
        for (int j = 0; j < 3; j++)
            R[i][j] = P0[i * 4 + 0] * P1[j * 4 + 0]
                    + P0[i * 4 + 1] * P1[j * 4 + 1]
                    + P0[i * 4 + 2] * P1[j * 4 + 2];
#pragma unroll
    for (int i = 0; i < 3; i++)
        t[i] = P0[i * 4 + 3]
             - (R[i][0] * P1[3] + R[i][1] * P1[7] + R[i][2] * P1[11]);

    const float inv_m = 128.0f / 63.0f;
    const float s = 64.0f / 63.0f;
#pragma unroll
    for (int i = 0; i < 3; i++) {
        g_M[n][i * 4 + 0] = s * R[i][0];
        g_M[n][i * 4 + 1] = s * R[i][1];
        g_M[n][i * 4 + 2] = s * R[i][2];
        g_M[n][i * 4 + 3] =
            32.0f * (t[i] * inv_m - (R[i][0] + R[i][1] + R[i][2])) + 31.5f;
    }
}

// blockIdx.z in [0,64): warp tiles (8 z-tiles x 8 pairs).
// blockIdx.z in [64,72): frame-0 copy blocks (512), overlapping DRAM copy.
__global__ __launch_bounds__(256) void warp_kernel(const float* __restrict__ vox,
                                                   float* __restrict__ out) {
    const int tid = threadIdx.x;

    if (blockIdx.z >= 64) {
        int cb = ((int)blockIdx.z - 64) * 64 + (int)blockIdx.y * 8 + (int)blockIdx.x;
        int batch = cb >> 8;
        int local = cb & 255;
        const float4* s4 = (const float4*)(vox + (size_t)batch * 5 * CVOL);
        float4* d4 = (float4*)(out + (size_t)batch * 5 * CVOL);
        int base = local * 4096 + tid;
#pragma unroll
        for (int i = 0; i < 16; i++)
            d4[base + i * 256] = s4[base + i * 256];
        return;
    }

    const int n = blockIdx.z >> 3;

    __shared__ float Ms[12];
    __shared__ int sO[3], sD[3];
    __shared__ int sSkip;
    __shared__ __align__(16) __half2 tile[2 * TILE_E];  // 43.7 KB

    if (tid < 12) Ms[tid] = g_M[n][tid];
    __syncthreads();

    const int bx0 = (int)blockIdx.x * 8;
    const int by0 = (int)blockIdx.y * 8;
    const int bz0 = (int)(blockIdx.z & 7) * 8;

    if (tid == 0) {
        int skip = 0;
#pragma unroll
        for (int i = 0; i < 3; i++) {
            float a = Ms[i * 4 + 0], b = Ms[i * 4 + 1], c = Ms[i * 4 + 2], d = Ms[i * 4 + 3];
            float xl = (float)bx0, xh = (float)(bx0 + 7);
            float yl = (float)by0, yh = (float)(by0 + 7);
            float zl = (float)bz0, zh = (float)(bz0 + 7);
            float fmin = d + fminf(a * xl, a * xh) + fminf(b * yl, b * yh) + fminf(c * zl, c * zh);
            float fmax = d + fmaxf(a * xl, a * xh) + fmaxf(b * yl, b * yh) + fmaxf(c * zl, c * zh);
            int o = (int)floorf(fmin);
            int dd = (int)floorf(fmax) + 2 - o;  // provably <= 15
            if (dd > 15) dd = 15;                // safety
            sO[i] = o;
            sD[i] = dd;
            skip |= (o > 63) | (o + dd <= 0);
        }
        sSkip = skip;
    }
    __syncthreads();

    const int b = n >> 2, k = n & 3;
    const int frame = b * 5 + 1 + k;
    const float* __restrict__ src = vox + (size_t)frame * CVOL;
    float* __restrict__ dstf = out + (size_t)frame * CVOL;

    const int lx = bx0 + (tid & 7);
    const int ly = by0 + ((tid >> 3) & 7);
    const int lz = bz0 + (tid >> 6);  // p=0: z, p=1: z+4
    const int dst0 = lz * GG + ly * G + lx;

    if (sSkip) {
#pragma unroll
        for (int c = 0; c < NCH; c++) {
            dstf[dst0 + c * GGG] = 0.0f;
            dstf[dst0 + 4 * GG + c * GGG] = 0.0f;
        }
        return;
    }

    const int ox = sO[0], oy = sO[1], oz = sO[2];
    const int dx = sD[0], dy = sD[1], dz = sD[2];
    const int xfrac = ox & 3;
    const int ox4 = ox - xfrac;
    const int nseg = (xfrac + dx + 3) >> 2;

    // ---- per-point weights & smem entry offsets (once, reused over 16 ch)
    float wzy[2][4], wxa[2][2];
    int soff[2];
#pragma unroll
    for (int p = 0; p < 2; p++) {
        float xf = (float)lx, yf = (float)ly, zf = (float)(lz + p * 4);
        float fx = fmaf(Ms[2], zf, fmaf(Ms[1], yf, fmaf(Ms[0], xf, Ms[3])));
        float fy = fmaf(Ms[6], zf, fmaf(Ms[5], yf, fmaf(Ms[4], xf, Ms[7])));
        float fz = fmaf(Ms[10], zf, fmaf(Ms[9], yf, fmaf(Ms[8], xf, Ms[11])));
        float xfl = floorf(fx), yfl = floorf(fy), zfl = floorf(fz);
        float tx = fx - xfl, ty = fy - yfl, tz = fz - zfl;
        int ix0 = (int)xfl, iy0 = (int)yfl, iz0 = (int)zfl;

        float wx0 = ((unsigned)ix0 < 64u) ? (1.0f - tx) : 0.0f;
        float wx1 = ((unsigned)(ix0 + 1) < 64u) ? tx : 0.0f;
        float wy0 = ((unsigned)iy0 < 64u) ? (1.0f - ty) : 0.0f;
        float wy1 = ((unsigned)(iy0 + 1) < 64u) ? ty : 0.0f;
        float wz0 = ((unsigned)iz0 < 64u) ? (1.0f - tz) : 0.0f;
        float wz1 = ((unsigned)(iz0 + 1) < 64u) ? tz : 0.0f;

        wzy[p][0] = wz0 * wy0; wzy[p][1] = wz0 * wy1;
        wzy[p][2] = wz1 * wy0; wzy[p][3] = wz1 * wy1;
        wxa[p][0] = wx0; wxa[p][1] = wx1;

        soff[p] = (iz0 - oz) * ZS2 + (iy0 - oy) * XP2 + (ix0 - ox4);
    }

    // ---- staging addresses (channel-invariant): dz*dy rows x nseg segments.
    // Segment s covers x = ox4+4s..+3 and writes 4 pair entries
    // (v0,v1)(v1,v2)(v2,v3)(v3,v4) as ONE STS.128. v4 comes from the next
    // thread's v.x via shfl (next flattened idx = next segment); lane 31
    // loads it as a scalar. Row-boundary garbage lands only in the final
    // entry of a row's last segment, which is never read.
    int lin[5], lin4[5], sof[5];
    bool act[5];
    const int rowlen = dy * nseg;
    const int total = dz * rowlen;
#pragma unroll
    for (int i = 0; i < 5; i++) {
        int idx = tid + i * 256;
        act[i] = idx < total;
        int zi = idx / rowlen;
        int r = idx - zi * rowlen;
        int yi = r / nseg;
        int s = r - yi * nseg;
        int zc = min(max(oz + zi, 0), 63);
        int yc = min(max(oy + yi, 0), 63);
        int l = zc * GG + yc * G + (ox4 + 4 * s);
        l = min(max(l, 0), GGG - 4);
        lin[i] = l;
        lin4[i] = min(l + 4, GGG - 1);
        sof[i] = zi * ZS2 + yi * XP2 + 4 * s;  // mult of 4 entries = 16B
    }
    const bool lane31 = (tid & 31) == 31;

    // ---- prologue: stage channel 0 into buffer 0
    {
        const float* __restrict__ sc = src;
#pragma unroll
        for (int i = 0; i < 5; i++) {
            float4 v;
            if (act[i]) v = __ldg((const float4*)(sc + lin[i]));
            float v4 = __shfl_down_sync(0xffffffffu, v.x, 1);
            if (lane31 && act[i]) v4 = __ldg(sc + lin4[i]);
            if (act[i]) {
                __half2 e0 = __floats2half2_rn(v.x, v.y);
                __half2 e1 = __floats2half2_rn(v.y, v.z);
                __half2 e2 = __floats2half2_rn(v.z, v.w);
                __half2 e3 = __floats2half2_rn(v.w, v4);
                uint4 pk;
                pk.x = *(unsigned*)&e0;
                pk.y = *(unsigned*)&e1;
                pk.z = *(unsigned*)&e2;
                pk.w = *(unsigned*)&e3;
                *(uint4*)&tile[sof[i]] = pk;
            }
        }
    }
    __syncthreads();

#pragma unroll 1
    for (int c = 0; c < NCH; c++) {
        // issue next channel's loads first (latency hides under consume)
        float4 r0, r1, r2, r3, r4;
        const bool have = (c + 1 < NCH);
        if (have) {
            const float* __restrict__ sn = src + (c + 1) * GGG;
            if (act[0]) r0 = __ldg((const float4*)(sn + lin[0]));
            if (act[1]) r1 = __ldg((const float4*)(sn + lin[1]));
            if (act[2]) r2 = __ldg((const float4*)(sn + lin[2]));
            if (act[3]) r3 = __ldg((const float4*)(sn + lin[3]));
            if (act[4]) r4 = __ldg((const float4*)(sn + lin[4]));
        }

        // consume channel c from buffer c&1: 4 LDS.32 per point
        const __half2* __restrict__ tb = tile + (c & 1) * TILE_E;
#pragma unroll
        for (int p = 0; p < 2; p++) {
            const int s = soff[p];
            float2 f0 = __half22float2(tb[s]);
            float2 f1 = __half22float2(tb[s + XP2]);
            float2 f2 = __half22float2(tb[s + ZS2]);
            float2 f3 = __half22float2(tb[s + ZS2 + XP2]);
            float t0 = fmaf(wxa[p][1], f0.y, wxa[p][0] * f0.x);
            float t1 = fmaf(wxa[p][1], f1.y, wxa[p][0] * f1.x);
            float t2 = fmaf(wxa[p][1], f2.y, wxa[p][0] * f2.x);
            float t3 = fmaf(wxa[p][1], f3.y, wxa[p][0] * f3.x);
            float acc = wzy[p][0] * t0;
            acc = fmaf(wzy[p][1], t1, acc);
            acc = fmaf(wzy[p][2], t2, acc);
            acc = fmaf(wzy[p][3], t3, acc);
            dstf[dst0 + p * (4 * GG) + c * GGG] = acc;
        }

        // store next channel into the other buffer
        if (have) {
            const float* __restrict__ sn = src + (c + 1) * GGG;
            __half2* __restrict__ tn = tile + ((c + 1) & 1) * TILE_E;
#pragma unroll
            for (int i = 0; i < 5; i++) {
                float4 v = (i == 0) ? r0 : (i == 1) ? r1 : (i == 2) ? r2
                         : (i == 3) ? r3 : r4;
                float v4 = __shfl_down_sync(0xffffffffu, v.x, 1);
                if (lane31 && act[i]) v4 = __ldg(sn + lin4[i]);
                if (act[i]) {
                    __half2 e0 = __floats2half2_rn(v.x, v.y);
                    __half2 e1 = __floats2half2_rn(v.y, v.z);
                    __half2 e2 = __floats2half2_rn(v.z, v.w);
                    __half2 e3 = __floats2half2_rn(v.w, v4);
                    uint4 pk;
                    pk.x = *(unsigned*)&e0;
                    pk.y = *(unsigned*)&e1;
                    pk.z = *(unsigned*)&e2;
                    pk.w = *(unsigned*)&e3;
                    *(uint4*)&tn[sof[i]] = pk;
                }
            }
        }
        __syncthreads();
    }
}

extern "C" void kernel_launch(void* const* d_in, const int* in_sizes, int n_in,
                              void* d_out, int out_size) {
    const float* vox   = (const float*)d_in[0];   // (2,5,16,64,64,64) fp32
    const float* poses = (const float*)d_in[1];   // (2,5,4,4) fp32
    float* out = (float*)d_out;

    xform_kernel<<<1, 32>>>(poses);

    dim3 block(256, 1, 1);
    dim3 grid(8, 8, 72);
    warp_kernel<<<grid, block>>>(vox, out);
}

// round 12
// speedup vs baseline: 1.1785x; 1.1785x over previous
#include <cuda_runtime.h>
#include <cstdint>

// Problem constants: B=2, t=5, C=16, G=64
#define G 64
#define GG 4096
#define GGG 262144
#define NCH 16
#define CVOL (NCH * GGG)
#define NPAIR 8

// fp32 tile, double-buffered, filled by cp.async.
// XP=24: warp bank decollision in y. ZS=364 = 15*24+4 (mod 32 = 12, mult of 4).
// 15 planes/rows suffice: AABB span <= 7*sqrt(3)*64/63 + 2 < 15.
#define XP 24
#define ZS 364
#define PLANES 15
#define TILE_F (PLANES * ZS)  // 5460 floats = 21.84 KB per buffer

__device__ float g_M[NPAIR][12];

__device__ __forceinline__ void cp_async16(uint32_t dst, const float* src) {
    asm volatile("cp.async.cg.shared.global [%0], [%1], 16;"
                 :: "r"(dst), "l"(src) : "memory");
}
__device__ __forceinline__ void cp_commit() {
    asm volatile("cp.async.commit_group;" ::: "memory");
}
__device__ __forceinline__ void cp_wait1() {
    asm volatile("cp.async.wait_group 1;" ::: "memory");
}
__device__ __forceinline__ void cp_wait0() {
    asm volatile("cp.async.wait_group 0;" ::: "memory");
}

__global__ void xform_kernel(const float* __restrict__ poses /* (2,5,4,4) */) {
    int n = threadIdx.x;
    if (n >= NPAIR) return;
    int b = n >> 2;
    int k = (n & 3) + 1;
    const float* P0 = poses + (size_t)(b * 5 + 0) * 16;
    const float* P1 = poses + (size_t)(b * 5 + k) * 16;

    // T = P0 @ inv(P1); P1 rigid => inv(P1) = [R1^T | -R1^T t1]
    float R[3][3], t[3];
#pragma unroll
    for (int i = 0; i < 3; i++)
#pragma unroll
        for (int j = 0; j < 3; j++)
            R[i][j] = P0[i * 4 + 0] * P1[j * 4 + 0]
                    + P0[i * 4 + 1] * P1[j * 4 + 1]
                    + P0[i * 4 + 2] * P1[j * 4 + 2];
#pragma unroll
    for (int i = 0; i < 3; i++)
        t[i] = P0[i * 4 + 3]
             - (R[i][0] * P1[3] + R[i][1] * P1[7] + R[i][2] * P1[11]);

    const float inv_m = 128.0f / 63.0f;
    const float s = 64.0f / 63.0f;
#pragma unroll
    for (int i = 0; i < 3; i++) {
        g_M[n][i * 4 + 0] = s * R[i][0];
        g_M[n][i * 4 + 1] = s * R[i][1];
        g_M[n][i * 4 + 2] = s * R[i][2];
        g_M[n][i * 4 + 3] =
            32.0f * (t[i] * inv_m - (R[i][0] + R[i][1] + R[i][2])) + 31.5f;
    }
}

// blockIdx.z in [0,64): warp tiles (8 z-tiles x 8 pairs).
// blockIdx.z in [64,72): frame-0 copy blocks (512), overlapping DRAM copy.
__global__ __launch_bounds__(256) void warp_kernel(const float* __restrict__ vox,
                                                   float* __restrict__ out) {
    const int tid = threadIdx.x;

    if (blockIdx.z >= 64) {
        int cb = ((int)blockIdx.z - 64) * 64 + (int)blockIdx.y * 8 + (int)blockIdx.x;
        int batch = cb >> 8;
        int local = cb & 255;
        const float4* s4 = (const float4*)(vox + (size_t)batch * 5 * CVOL);
        float4* d4 = (float4*)(out + (size_t)batch * 5 * CVOL);
        int base = local * 4096 + tid;
#pragma unroll
        for (int i = 0; i < 16; i++)
            d4[base + i * 256] = s4[base + i * 256];
        return;
    }

    const int n = blockIdx.z >> 3;

    __shared__ float Ms[12];
    __shared__ int sO[3], sD[3];
    __shared__ int sSkip;
    __shared__ __align__(16) float tile[2 * TILE_F];  // 43.7 KB

    if (tid < 12) Ms[tid] = g_M[n][tid];
    __syncthreads();

    const int bx0 = (int)blockIdx.x * 8;
    const int by0 = (int)blockIdx.y * 8;
    const int bz0 = (int)(blockIdx.z & 7) * 8;

    if (tid == 0) {
        int skip = 0;
#pragma unroll
        for (int i = 0; i < 3; i++) {
            float a = Ms[i * 4 + 0], b = Ms[i * 4 + 1], c = Ms[i * 4 + 2], d = Ms[i * 4 + 3];
            float xl = (float)bx0, xh = (float)(bx0 + 7);
            float yl = (float)by0, yh = (float)(by0 + 7);
            float zl = (float)bz0, zh = (float)(bz0 + 7);
            float fmin = d + fminf(a * xl, a * xh) + fminf(b * yl, b * yh) + fminf(c * zl, c * zh);
            float fmax = d + fmaxf(a * xl, a * xh) + fmaxf(b * yl, b * yh) + fmaxf(c * zl, c * zh);
            int o = (int)floorf(fmin);
            int dd = (int)floorf(fmax) + 2 - o;  // provably <= 14
            if (dd > PLANES) dd = PLANES;        // safety
            sO[i] = o;
            sD[i] = dd;
            skip |= (o > 63) | (o + dd <= 0);
        }
        sSkip = skip;
    }
    __syncthreads();

    const int b = n >> 2, k = n & 3;
    const int frame = b * 5 + 1 + k;
    const float* __restrict__ src = vox + (size_t)frame * CVOL;
    float* __restrict__ dstf = out + (size_t)frame * CVOL;

    // x-pair mapping: thread owns points (lx, lx+1) at (ly, lz)
    const int lx = bx0 + ((tid & 3) << 1);
    const int ly = by0 + ((tid >> 2) & 7);
    const int lz = bz0 + (tid >> 5);
    const int dst0 = lz * GG + ly * G + lx;  // even -> 8B aligned

    if (sSkip) {
#pragma unroll
        for (int c = 0; c < NCH; c++)
            *(float2*)(dstf + dst0 + c * GGG) = make_float2(0.0f, 0.0f);
        return;
    }

    const int ox = sO[0], oy = sO[1], oz = sO[2];
    const int dx = sD[0], dy = sD[1], dz = sD[2];
    const int xfrac = ox & 3;
    const int ox4 = ox - xfrac;
    const int nseg = (xfrac + dx + 3) >> 2;

    // ---- per-point weights & smem offsets (computed once, reused over 16 ch)
    float wzy[2][4], wxa[2][2];
    int soff[2];
    {
        float xf = (float)lx, yf = (float)ly, zf = (float)lz;
        float fx = fmaf(Ms[2], zf, fmaf(Ms[1], yf, fmaf(Ms[0], xf, Ms[3])));
        float fy = fmaf(Ms[6], zf, fmaf(Ms[5], yf, fmaf(Ms[4], xf, Ms[7])));
        float fz = fmaf(Ms[10], zf, fmaf(Ms[9], yf, fmaf(Ms[8], xf, Ms[11])));
#pragma unroll
        for (int p = 0; p < 2; p++) {
            float xfl = floorf(fx), yfl = floorf(fy), zfl = floorf(fz);
            float tx = fx - xfl, ty = fy - yfl, tz = fz - zfl;
            int ix0 = (int)xfl, iy0 = (int)yfl, iz0 = (int)zfl;

            float wx0 = ((unsigned)ix0 < 64u) ? (1.0f - tx) : 0.0f;
            float wx1 = ((unsigned)(ix0 + 1) < 64u) ? tx : 0.0f;
            float wy0 = ((unsigned)iy0 < 64u) ? (1.0f - ty) : 0.0f;
            float wy1 = ((unsigned)(iy0 + 1) < 64u) ? ty : 0.0f;
            float wz0 = ((unsigned)iz0 < 64u) ? (1.0f - tz) : 0.0f;
            float wz1 = ((unsigned)(iz0 + 1) < 64u) ? tz : 0.0f;

            wzy[p][0] = wz0 * wy0; wzy[p][1] = wz0 * wy1;
            wzy[p][2] = wz1 * wy0; wzy[p][3] = wz1 * wy1;
            wxa[p][0] = wx0; wxa[p][1] = wx1;

            soff[p] = (iz0 - oz) * ZS + (iy0 - oy) * XP + (ix0 - ox4);

            // advance to second point (x+1)
            fx += Ms[0]; fy += Ms[4]; fz += Ms[8];
        }
    }

    // ---- staging addresses (channel-invariant): dz*dy rows x nseg segments.
    // 16B cp.async per segment; OOB segments carry zero weight, clamp only.
    int lin[5], sof[5];
    bool act[5];
    const int rowlen = dy * nseg;
    const int total = dz * rowlen;
#pragma unroll
    for (int i = 0; i < 5; i++) {
        int idx = tid + i * 256;
        act[i] = idx < total;
        int zi = idx / rowlen;
        int r = idx - zi * rowlen;
        int yi = r / nseg;
        int s = r - yi * nseg;
        int zc = min(max(oz + zi, 0), 63);
        int yc = min(max(oy + yi, 0), 63);
        int l = zc * GG + yc * G + (ox4 + 4 * s);
        lin[i] = min(max(l, 0), GGG - 4);
        sof[i] = zi * ZS + yi * XP + 4 * s;  // mult of 4 floats = 16B aligned
    }

    const uint32_t tile_sa = (uint32_t)__cvta_generic_to_shared(tile);

    // ---- prologue: stage channel 0 into buffer 0
    {
        const float* __restrict__ sc = src;
#pragma unroll
        for (int i = 0; i < 5; i++)
            if (act[i]) cp_async16(tile_sa + (uint32_t)(sof[i] * 4), sc + lin[i]);
        cp_commit();
    }

#pragma unroll 1
    for (int c = 0; c < NCH; c++) {
        const bool have = (c + 1 < NCH);
        // issue next channel into the other buffer (safe: that buffer's
        // consumers finished before the end-of-iter barrier last round)
        if (have) {
            const float* __restrict__ sn = src + (c + 1) * GGG;
            const uint32_t bofs = tile_sa + (uint32_t)((((c + 1) & 1) * TILE_F) * 4);
#pragma unroll
            for (int i = 0; i < 5; i++)
                if (act[i]) cp_async16(bofs + (uint32_t)(sof[i] * 4), sn + lin[i]);
            cp_commit();
            cp_wait1();   // channel c's group complete
        } else {
            cp_commit();  // empty group keeps accounting simple
            cp_wait0();
        }
        __syncthreads();  // staged data visible block-wide

        const float* __restrict__ tb = tile + (c & 1) * TILE_F;
        float acc2[2];
#pragma unroll
        for (int p = 0; p < 2; p++) {
            const int s = soff[p];
            float t0 = fmaf(wxa[p][1], tb[s + 1], wxa[p][0] * tb[s]);
            float t1 = fmaf(wxa[p][1], tb[s + XP + 1], wxa[p][0] * tb[s + XP]);
            float t2 = fmaf(wxa[p][1], tb[s + ZS + 1], wxa[p][0] * tb[s + ZS]);
            float t3 = fmaf(wxa[p][1], tb[s + ZS + XP + 1], wxa[p][0] * tb[s + ZS + XP]);
            float acc = wzy[p][0] * t0;
            acc = fmaf(wzy[p][1], t1, acc);
            acc = fmaf(wzy[p][2], t2, acc);
            acc = fmaf(wzy[p][3], t3, acc);
            acc2[p] = acc;
        }
        *(float2*)(dstf + dst0 + c * GGG) = make_float2(acc2[0], acc2[1]);

        __syncthreads();  // consume done before next iter overwrites buf c&1
    }
}

extern "C" void kernel_launch(void* const* d_in, const int* in_sizes, int n_in,
                              void* d_out, int out_size) {
    const float* vox   = (const float*)d_in[0];   // (2,5,16,64,64,64) fp32
    const float* poses = (const float*)d_in[1];   // (2,5,4,4) fp32
    float* out = (float*)d_out;

    xform_kernel<<<1, 32>>>(poses);

    dim3 block(256, 1, 1);
    dim3 grid(8, 8, 72);
    warp_kernel<<<grid, block>>>(vox, out);
}

// round 13
// speedup vs baseline: 1.2217x; 1.0366x over previous
#include <cuda_runtime.h>
#include <cstdint>

// Problem constants: B=2, t=5, C=16, G=64
#define G 64
#define GG 4096
#define GGG 262144
#define NCH 16
#define CVOL (NCH * GGG)
#define NPAIR 8

// fp32 tile, double-buffered, filled by cp.async.
// XP=20: with the warp's 8 y-rows, y*20 mod 32 = {0,20,8,28,16,4,24,12} ->
// all 8 rows on disjoint 4-bank ranges (conflict-free consume in y).
// ZS=324 = 15*20+24 (mod 32 = 4, mult of 4): z-jitter lanes offset by 4 banks.
// 15 planes/rows suffice (AABB span <= 7*sqrt(3)*64/63 + 2 < 15); nseg <= 5
// and 5 segs * 4 floats = 20 = XP exactly.
#define XP 20
#define ZS 324
#define PLANES 15
#define TILE_F (PLANES * ZS)  // 4860 floats = 19.44 KB per buffer

__device__ float g_M[NPAIR][12];

__device__ __forceinline__ void cp_async16(uint32_t dst, const float* src) {
    asm volatile("cp.async.cg.shared.global [%0], [%1], 16;"
                 :: "r"(dst), "l"(src) : "memory");
}
__device__ __forceinline__ void cp_commit() {
    asm volatile("cp.async.commit_group;" ::: "memory");
}
__device__ __forceinline__ void cp_wait1() {
    asm volatile("cp.async.wait_group 1;" ::: "memory");
}
__device__ __forceinline__ void cp_wait0() {
    asm volatile("cp.async.wait_group 0;" ::: "memory");
}

__global__ void xform_kernel(const float* __restrict__ poses /* (2,5,4,4) */) {
    int n = threadIdx.x;
    if (n >= NPAIR) return;
    int b = n >> 2;
    int k = (n & 3) + 1;
    const float* P0 = poses + (size_t)(b * 5 + 0) * 16;
    const float* P1 = poses + (size_t)(b * 5 + k) * 16;

    // T = P0 @ inv(P1); P1 rigid => inv(P1) = [R1^T | -R1^T t1]
    float R[3][3], t[3];
#pragma unroll
    for (int i = 0; i < 3; i++)
#pragma unroll
        for (int j = 0; j < 3; j++)
            R[i][j] = P0[i * 4 + 0] * P1[j * 4 + 0]
                    + P0[i * 4 + 1] * P1[j * 4 + 1]
                    + P0[i * 4 + 2] * P1[j * 4 + 2];
#pragma unroll
    for (int i = 0; i < 3; i++)
        t[i] = P0[i * 4 + 3]
             - (R[i][0] * P1[3] + R[i][1] * P1[7] + R[i][2] * P1[11]);

    const float inv_m = 128.0f / 63.0f;
    const float s = 64.0f / 63.0f;
#pragma unroll
    for (int i = 0; i < 3; i++) {
        g_M[n][i * 4 + 0] = s * R[i][0];
        g_M[n][i * 4 + 1] = s * R[i][1];
        g_M[n][i * 4 + 2] = s * R[i][2];
        g_M[n][i * 4 + 3] =
            32.0f * (t[i] * inv_m - (R[i][0] + R[i][1] + R[i][2])) + 31.5f;
    }
}

// blockIdx.z in [0,64): warp tiles (8 z-tiles x 8 pairs).
// blockIdx.z in [64,72): frame-0 copy blocks (512), overlapping DRAM copy.
__global__ __launch_bounds__(256) void warp_kernel(const float* __restrict__ vox,
                                                   float* __restrict__ out) {
    const int tid = threadIdx.x;

    if (blockIdx.z >= 64) {
        int cb = ((int)blockIdx.z - 64) * 64 + (int)blockIdx.y * 8 + (int)blockIdx.x;
        int batch = cb >> 8;
        int local = cb & 255;
        const float4* s4 = (const float4*)(vox + (size_t)batch * 5 * CVOL);
        float4* d4 = (float4*)(out + (size_t)batch * 5 * CVOL);
        int base = local * 4096 + tid;
#pragma unroll
        for (int i = 0; i < 16; i++)
            d4[base + i * 256] = s4[base + i * 256];
        return;
    }

    const int n = blockIdx.z >> 3;

    __shared__ float Ms[12];
    __shared__ int sO[3], sD[3];
    __shared__ int sSkip;
    __shared__ __align__(16) float tile[2 * TILE_F];  // 38.9 KB

    if (tid < 12) Ms[tid] = g_M[n][tid];
    __syncthreads();

    const int bx0 = (int)blockIdx.x * 8;
    const int by0 = (int)blockIdx.y * 8;
    const int bz0 = (int)(blockIdx.z & 7) * 8;

    if (tid == 0) {
        int skip = 0;
#pragma unroll
        for (int i = 0; i < 3; i++) {
            float a = Ms[i * 4 + 0], b = Ms[i * 4 + 1], c = Ms[i * 4 + 2], d = Ms[i * 4 + 3];
            float xl = (float)bx0, xh = (float)(bx0 + 7);
            float yl = (float)by0, yh = (float)(by0 + 7);
            float zl = (float)bz0, zh = (float)(bz0 + 7);
            float fmin = d + fminf(a * xl, a * xh) + fminf(b * yl, b * yh) + fminf(c * zl, c * zh);
            float fmax = d + fmaxf(a * xl, a * xh) + fmaxf(b * yl, b * yh) + fmaxf(c * zl, c * zh);
            int o = (int)floorf(fmin);
            int dd = (int)floorf(fmax) + 2 - o;  // provably <= 15
            if (dd > PLANES) dd = PLANES;        // safety
            sO[i] = o;
            sD[i] = dd;
            skip |= (o > 63) | (o + dd <= 0);
        }
        sSkip = skip;
    }
    __syncthreads();

    const int b = n >> 2, k = n & 3;
    const int frame = b * 5 + 1 + k;
    const float* __restrict__ src = vox + (size_t)frame * CVOL;
    float* __restrict__ dstf = out + (size_t)frame * CVOL;

    // x-pair mapping: thread owns points (lx, lx+1) at (ly, lz)
    const int lx = bx0 + ((tid & 3) << 1);
    const int ly = by0 + ((tid >> 2) & 7);
    const int lz = bz0 + (tid >> 5);
    const int dst0 = lz * GG + ly * G + lx;  // even -> 8B aligned

    if (sSkip) {
#pragma unroll
        for (int c = 0; c < NCH; c++)
            *(float2*)(dstf + dst0 + c * GGG) = make_float2(0.0f, 0.0f);
        return;
    }

    const int ox = sO[0], oy = sO[1], oz = sO[2];
    const int dx = sD[0], dy = sD[1], dz = sD[2];
    const int xfrac = ox & 3;
    const int ox4 = ox - xfrac;
    const int nseg = (xfrac + dx + 3) >> 2;

    // ---- per-point weights & smem offsets (computed once, reused over 16 ch)
    float wzy[2][4], wxa[2][2];
    int soff[2];
    {
        float xf = (float)lx, yf = (float)ly, zf = (float)lz;
        float fx = fmaf(Ms[2], zf, fmaf(Ms[1], yf, fmaf(Ms[0], xf, Ms[3])));
        float fy = fmaf(Ms[6], zf, fmaf(Ms[5], yf, fmaf(Ms[4], xf, Ms[7])));
        float fz = fmaf(Ms[10], zf, fmaf(Ms[9], yf, fmaf(Ms[8], xf, Ms[11])));
#pragma unroll
        for (int p = 0; p < 2; p++) {
            float xfl = floorf(fx), yfl = floorf(fy), zfl = floorf(fz);
            float tx = fx - xfl, ty = fy - yfl, tz = fz - zfl;
            int ix0 = (int)xfl, iy0 = (int)yfl, iz0 = (int)zfl;

            float wx0 = ((unsigned)ix0 < 64u) ? (1.0f - tx) : 0.0f;
            float wx1 = ((unsigned)(ix0 + 1) < 64u) ? tx : 0.0f;
            float wy0 = ((unsigned)iy0 < 64u) ? (1.0f - ty) : 0.0f;
            float wy1 = ((unsigned)(iy0 + 1) < 64u) ? ty : 0.0f;
            float wz0 = ((unsigned)iz0 < 64u) ? (1.0f - tz) : 0.0f;
            float wz1 = ((unsigned)(iz0 + 1) < 64u) ? tz : 0.0f;

            wzy[p][0] = wz0 * wy0; wzy[p][1] = wz0 * wy1;
            wzy[p][2] = wz1 * wy0; wzy[p][3] = wz1 * wy1;
            wxa[p][0] = wx0; wxa[p][1] = wx1;

            soff[p] = (iz0 - oz) * ZS + (iy0 - oy) * XP + (ix0 - ox4);

            // advance to second point (x+1)
            fx += Ms[0]; fy += Ms[4]; fz += Ms[8];
        }
    }

    // ---- staging addresses (channel-invariant): dz*dy rows x nseg segments.
    // 16B cp.async per segment; OOB segments carry zero weight, clamp only.
    int lin[5], sof[5];
    bool act[5];
    const int rowlen = dy * nseg;
    const int total = dz * rowlen;
#pragma unroll
    for (int i = 0; i < 5; i++) {
        int idx = tid + i * 256;
        act[i] = idx < total;
        int zi = idx / rowlen;
        int r = idx - zi * rowlen;
        int yi = r / nseg;
        int s = r - yi * nseg;
        int zc = min(max(oz + zi, 0), 63);
        int yc = min(max(oy + yi, 0), 63);
        int l = zc * GG + yc * G + (ox4 + 4 * s);
        lin[i] = min(max(l, 0), GGG - 4);
        sof[i] = zi * ZS + yi * XP + 4 * s;  // mult of 4 floats = 16B aligned
    }

    const uint32_t tile_sa = (uint32_t)__cvta_generic_to_shared(tile);

    // ---- prologue: stage channel 0 into buffer 0
    {
        const float* __restrict__ sc = src;
#pragma unroll
        for (int i = 0; i < 5; i++)
            if (act[i]) cp_async16(tile_sa + (uint32_t)(sof[i] * 4), sc + lin[i]);
        cp_commit();
    }

#pragma unroll 1
    for (int c = 0; c < NCH; c++) {
        const bool have = (c + 1 < NCH);
        // issue next channel into the other buffer (safe: that buffer's
        // consumers finished before the end-of-iter barrier last round)
        if (have) {
            const float* __restrict__ sn = src + (c + 1) * GGG;
            const uint32_t bofs = tile_sa + (uint32_t)((((c + 1) & 1) * TILE_F) * 4);
#pragma unroll
            for (int i = 0; i < 5; i++)
                if (act[i]) cp_async16(bofs + (uint32_t)(sof[i] * 4), sn + lin[i]);
            cp_commit();
            cp_wait1();   // channel c's group complete
        } else {
            cp_commit();  // empty group keeps accounting simple
            cp_wait0();
        }
        __syncthreads();  // staged data visible block-wide

        const float* __restrict__ tb = tile + (c & 1) * TILE_F;
        float acc2[2];
#pragma unroll
        for (int p = 0; p < 2; p++) {
            const int s = soff[p];
            float t0 = fmaf(wxa[p][1], tb[s + 1], wxa[p][0] * tb[s]);
            float t1 = fmaf(wxa[p][1], tb[s + XP + 1], wxa[p][0] * tb[s + XP]);
            float t2 = fmaf(wxa[p][1], tb[s + ZS + 1], wxa[p][0] * tb[s + ZS]);
            float t3 = fmaf(wxa[p][1], tb[s + ZS + XP + 1], wxa[p][0] * tb[s + ZS + XP]);
            float acc = wzy[p][0] * t0;
            acc = fmaf(wzy[p][1], t1, acc);
            acc = fmaf(wzy[p][2], t2, acc);
            acc = fmaf(wzy[p][3], t3, acc);
            acc2[p] = acc;
        }
        *(float2*)(dstf + dst0 + c * GGG) = make_float2(acc2[0], acc2[1]);

        __syncthreads();  // consume done before next iter overwrites buf c&1
    }
}

extern "C" void kernel_launch(void* const* d_in, const int* in_sizes, int n_in,
                              void* d_out, int out_size) {
    const float* vox   = (const float*)d_in[0];   // (2,5,16,64,64,64) fp32
    const float* poses = (const float*)d_in[1];   // (2,5,4,4) fp32
    float* out = (float*)d_out;

    xform_kernel<<<1, 32>>>(poses);

    dim3 block(256, 1, 1);
    dim3 grid(8, 8, 72);
    warp_kernel<<<grid, block>>>(vox, out);
}